// round 2
// baseline (speedup 1.0000x reference)
#include <cuda_runtime.h>
#include <math.h>

#define B_ 128
#define N_ 1369
#define F_ 384
#define H_ 8
#define C_ 512

// Scratch (device globals; no allocations allowed)
__device__ float g_Q[B_ * C_];        // (B, 512)  projected query
__device__ float g_qk[B_ * H_ * F_];  // (B, H, 384) query folded through Wk, pre-scaled
__device__ float g_ctx[B_ * H_ * F_]; // (B, H, 384) softmax-weighted dino context

// ---------- packed f32x2 helpers ----------
static __device__ __forceinline__ unsigned long long pk2(float lo, float hi) {
    unsigned long long r;
    asm("mov.b64 %0, {%1, %2};" : "=l"(r) : "f"(lo), "f"(hi));
    return r;
}
static __device__ __forceinline__ void upk2(unsigned long long v, float& lo, float& hi) {
    asm("mov.b64 {%0, %1}, %2;" : "=f"(lo), "=f"(hi) : "l"(v));
}
static __device__ __forceinline__ void ffma2(unsigned long long& d,
                                             unsigned long long a,
                                             unsigned long long b) {
    asm("fma.rn.f32x2 %0, %1, %2, %0;" : "+l"(d) : "l"(a), "l"(b));
}

// ---------- kernel 1: Q = clip @ Wq + bq ----------
// grid (8 j-tiles, 16 b-groups), 64 threads. Each thread: one column j, 8 batches.
__global__ __launch_bounds__(64) void k_qproj(const float* __restrict__ clip,
                                              const float* __restrict__ Wq,
                                              const float* __restrict__ bq) {
    int j = blockIdx.x * 64 + threadIdx.x;
    int b0 = blockIdx.y * 8;
    __shared__ float ct[C_ * 8];  // [c][bb]
    for (int idx = threadIdx.x; idx < 8 * C_; idx += 64) {
        int bb = idx >> 9;
        int c = idx & (C_ - 1);
        ct[c * 8 + bb] = clip[(b0 + bb) * C_ + c];
    }
    __syncthreads();
    float acc[8];
    float bqv = bq[j];
#pragma unroll
    for (int bb = 0; bb < 8; bb++) acc[bb] = bqv;
#pragma unroll 4
    for (int c = 0; c < C_; c++) {
        float wq = __ldg(&Wq[c * C_ + j]);
        float4 a = *(const float4*)&ct[c * 8];
        float4 b4 = *(const float4*)&ct[c * 8 + 4];
        acc[0] += a.x * wq; acc[1] += a.y * wq;
        acc[2] += a.z * wq; acc[3] += a.w * wq;
        acc[4] += b4.x * wq; acc[5] += b4.y * wq;
        acc[6] += b4.z * wq; acc[7] += b4.w * wq;
    }
#pragma unroll
    for (int bb = 0; bb < 8; bb++) g_Q[(b0 + bb) * C_ + j] = acc[bb];
}

// ---------- kernel 2: qk[b,h,f] = (sum_d Q[b,h*64+d] * Wk[f, h*64+d]) / (8*temp) ----------
// grid 64 (2 b per block), 384 threads (thread = f).
__global__ __launch_bounds__(384) void k_qk(const float* __restrict__ Wk,
                                            const float* __restrict__ temp) {
    int b0 = blockIdx.x * 2;
    int f = threadIdx.x;
    __shared__ float Qs[2 * C_];
    for (int idx = threadIdx.x; idx < 2 * C_; idx += 384)
        Qs[idx] = g_Q[b0 * C_ + idx];
    __syncthreads();
    float inv = 1.0f / (8.0f * temp[0]);
    const float4* wk = (const float4*)(Wk + (size_t)f * C_);
    for (int h = 0; h < H_; h++) {
        float a0 = 0.f, a1 = 0.f;
#pragma unroll
        for (int t = 0; t < 16; t++) {
            float4 w4 = __ldg(wk + h * 16 + t);
            float4 qa = *(const float4*)&Qs[h * 64 + t * 4];
            float4 qb = *(const float4*)&Qs[C_ + h * 64 + t * 4];
            a0 += w4.x * qa.x + w4.y * qa.y + w4.z * qa.z + w4.w * qa.w;
            a1 += w4.x * qb.x + w4.y * qb.y + w4.z * qb.z + w4.w * qb.w;
        }
        g_qk[((size_t)b0 * H_ + h) * F_ + f] = a0 * inv;
        g_qk[((size_t)(b0 + 1) * H_ + h) * F_ + f] = a1 * inv;
    }
}

// ---------- kernel 3 (main): single fused pass over dino ----------
// grid 128 (one block per b), 384 threads = 12 warps.
// Warp w: heads [4*(w&1), 4*(w&1)+4), rows n ≡ (w>>1) (mod 6).
// Per lane: 12 features (3 float4 chunks, interleaved), qk + ctx in packed f32x2 regs.
__global__ __launch_bounds__(384, 1) void k_attn(const float* __restrict__ dino) {
    int b = blockIdx.x;
    int tid = threadIdx.x;
    int w = tid >> 5, lane = tid & 31;
    int half = w & 1;   // which 4 heads
    int rg = w >> 1;    // row group 0..5

    __shared__ float sctx[H_ * F_];
    __shared__ float ssum[H_];
    for (int i = tid; i < H_ * F_; i += 384) sctx[i] = 0.f;
    if (tid < H_) ssum[tid] = 0.f;
    __syncthreads();

    // load qk for my 4 heads into packed regs
    unsigned long long qk2[4][6];
#pragma unroll
    for (int h = 0; h < 4; h++) {
#pragma unroll
        for (int c = 0; c < 3; c++) {
            float4 v = *(const float4*)&g_qk[((size_t)b * H_ + half * 4 + h) * F_ +
                                             (c * 32 + lane) * 4];
            qk2[h][2 * c] = pk2(v.x, v.y);
            qk2[h][2 * c + 1] = pk2(v.z, v.w);
        }
    }
    unsigned long long ctx2[4][6];
#pragma unroll
    for (int h = 0; h < 4; h++)
#pragma unroll
        for (int i = 0; i < 6; i++) ctx2[h][i] = 0ull;
    float s[4] = {0.f, 0.f, 0.f, 0.f};

    const float4* dbase = (const float4*)(dino + (size_t)b * N_ * F_);
    int n = rg;
    const float4* rp = dbase + (size_t)n * (F_ / 4) + lane;
    float4 p0 = __ldg(rp), p1 = __ldg(rp + 32), p2 = __ldg(rp + 64);

    while (n < N_) {
        float4 d0 = p0, d1 = p1, d2 = p2;
        int nn = n + 6;
        if (nn < N_) {
            const float4* np = dbase + (size_t)nn * (F_ / 4) + lane;
            p0 = __ldg(np); p1 = __ldg(np + 32); p2 = __ldg(np + 64);
        }
        unsigned long long dd[6] = {pk2(d0.x, d0.y), pk2(d0.z, d0.w),
                                    pk2(d1.x, d1.y), pk2(d1.z, d1.w),
                                    pk2(d2.x, d2.y), pk2(d2.z, d2.w)};
        // per-head partial dot (packed), then warp butterfly reduce
        float p[4];
#pragma unroll
        for (int h = 0; h < 4; h++) {
            unsigned long long acc = 0ull;
#pragma unroll
            for (int i = 0; i < 6; i++) ffma2(acc, dd[i], qk2[h][i]);
            float lo, hi;
            upk2(acc, lo, hi);
            p[h] = lo + hi;
        }
#pragma unroll
        for (int h = 0; h < 4; h++) {
#pragma unroll
            for (int o = 16; o; o >>= 1)
                p[h] += __shfl_xor_sync(0xffffffffu, p[h], o);
        }
        // softmax weights (no max subtraction needed: |logit| <~ 3) + ctx accumulate
#pragma unroll
        for (int h = 0; h < 4; h++) {
            float wgt = __expf(p[h]);
            s[h] += wgt;
            unsigned long long w2 = pk2(wgt, wgt);
#pragma unroll
            for (int i = 0; i < 6; i++) ffma2(ctx2[h][i], dd[i], w2);
        }
        n = nn;
    }

    // combine partials across the 6 row-group warps via smem atomics
#pragma unroll
    for (int h = 0; h < 4; h++) {
        int gh = half * 4 + h;
#pragma unroll
        for (int i = 0; i < 6; i++) {
            float lo, hi;
            upk2(ctx2[h][i], lo, hi);
            int fbase = ((i >> 1) * 32 + lane) * 4 + (i & 1) * 2;
            atomicAdd(&sctx[gh * F_ + fbase], lo);
            atomicAdd(&sctx[gh * F_ + fbase + 1], hi);
        }
        if (lane == 0) atomicAdd(&ssum[gh], s[h]);
    }
    __syncthreads();
    for (int i = tid; i < H_ * F_; i += 384) {
        int h = i / F_;
        g_ctx[(size_t)b * H_ * F_ + i] = sctx[i] / ssum[h];
    }
}

// ---------- kernel 4: out = ctx @ Wv + bv, then LayerNorm ----------
// grid 64 (2 b per block), 512 threads (thread = output column j).
__global__ __launch_bounds__(512) void k_out(const float* __restrict__ Wv,
                                             const float* __restrict__ bv,
                                             const float* __restrict__ gamma,
                                             const float* __restrict__ beta,
                                             float* __restrict__ out) {
    int b0 = blockIdx.x * 2;
    int j = threadIdx.x;
    __shared__ float cs[2 * H_ * F_];
    __shared__ float rbuf[64];   // [4 kinds][16 warps]
    __shared__ float stats[4];   // mu0, rstd0, mu1, rstd1
    for (int idx = j; idx < 2 * H_ * F_; idx += 512)
        cs[idx] = g_ctx[(size_t)b0 * H_ * F_ + idx];
    __syncthreads();

    int h = j >> 6;
    float a0 = bv[j], a1 = a0;
    const float* wvp = Wv + j;
    const float* c0 = &cs[h * F_];
    const float* c1 = &cs[H_ * F_ + h * F_];
#pragma unroll 4
    for (int f = 0; f < F_; f++) {
        float wv = __ldg(wvp + (size_t)f * C_);
        a0 += c0[f] * wv;
        a1 += c1[f] * wv;
    }

    // LayerNorm reductions (sum, sumsq per batch)
    int wid = j >> 5, lane = j & 31;
    float s0 = a0, q0 = a0 * a0, s1 = a1, q1 = a1 * a1;
#pragma unroll
    for (int o = 16; o; o >>= 1) {
        s0 += __shfl_xor_sync(0xffffffffu, s0, o);
        q0 += __shfl_xor_sync(0xffffffffu, q0, o);
        s1 += __shfl_xor_sync(0xffffffffu, s1, o);
        q1 += __shfl_xor_sync(0xffffffffu, q1, o);
    }
    if (lane == 0) {
        rbuf[wid] = s0;
        rbuf[16 + wid] = q0;
        rbuf[32 + wid] = s1;
        rbuf[48 + wid] = q1;
    }
    __syncthreads();
    if (j < 2) {
        float sum = 0.f, sq = 0.f;
#pragma unroll
        for (int k = 0; k < 16; k++) {
            sum += rbuf[j * 32 + k];
            sq += rbuf[j * 32 + 16 + k];
        }
        float mu = sum * (1.0f / C_);
        float var = sq * (1.0f / C_) - mu * mu;
        stats[j * 2] = mu;
        stats[j * 2 + 1] = rsqrtf(var + 1e-5f);
    }
    __syncthreads();
    float g = gamma[j], be = beta[j];
    out[(size_t)b0 * C_ + j] = (a0 - stats[0]) * stats[1] * g + be;
    out[(size_t)(b0 + 1) * C_ + j] = (a1 - stats[2]) * stats[3] * g + be;
}

extern "C" void kernel_launch(void* const* d_in, const int* in_sizes, int n_in,
                              void* d_out, int out_size) {
    const float* dino = (const float*)d_in[0];
    const float* clip = (const float*)d_in[1];
    const float* Wq = (const float*)d_in[2];
    const float* bq = (const float*)d_in[3];
    const float* Wk = (const float*)d_in[4];
    // d_in[5] = bk: cancels exactly in softmax (n-invariant logit shift)
    const float* Wv = (const float*)d_in[6];
    const float* bv = (const float*)d_in[7];
    const float* temp = (const float*)d_in[8];
    const float* gamma = (const float*)d_in[9];
    const float* beta = (const float*)d_in[10];
    float* out = (float*)d_out;

    k_qproj<<<dim3(8, 16), 64>>>(clip, Wq, bq);
    k_qk<<<64, 384>>>(Wk, temp);
    k_attn<<<128, 384>>>(dino);
    k_out<<<64, 512>>>(Wv, bv, gamma, beta, out);
}

// round 3
// speedup vs baseline: 1.3890x; 1.3890x over previous
#include <cuda_runtime.h>
#include <math.h>

#define B_ 128
#define N_ 1369
#define F_ 384
#define H_ 8
#define C_ 512

// Scratch (device globals; no allocations allowed)
__device__ float g_Q[B_ * C_];        // (B, 512)  projected query
__device__ float g_qk[B_ * H_ * F_];  // (B, H, 384) query folded through Wk, pre-scaled

// ---------- packed f32x2 helpers ----------
static __device__ __forceinline__ unsigned long long pk2(float lo, float hi) {
    unsigned long long r;
    asm("mov.b64 %0, {%1, %2};" : "=l"(r) : "f"(lo), "f"(hi));
    return r;
}
static __device__ __forceinline__ void upk2(unsigned long long v, float& lo, float& hi) {
    asm("mov.b64 {%0, %1}, %2;" : "=f"(lo), "=f"(hi) : "l"(v));
}
static __device__ __forceinline__ void ffma2(unsigned long long& d,
                                             unsigned long long a,
                                             unsigned long long b) {
    asm("fma.rn.f32x2 %0, %1, %2, %0;" : "+l"(d) : "l"(a), "l"(b));
}

// ---------- kernel 1: Q = clip @ Wq + bq ----------
// grid (8 j-tiles, 16 b-groups), 256 threads = 64 j-lanes x 4 c-quarters.
// Each thread: partial dot over 128 c's for 8 batches; smem reduce of the 4 partials.
__global__ __launch_bounds__(256) void k_qproj(const float* __restrict__ clip,
                                               const float* __restrict__ Wq,
                                               const float* __restrict__ bq) {
    int jl = threadIdx.x & 63;
    int cq = threadIdx.x >> 6;
    int j = blockIdx.x * 64 + jl;
    int b0 = blockIdx.y * 8;
    __shared__ float ct[C_ * 8];      // [c][bb]
    __shared__ float pr[4][64][9];    // padded (9) for conflict-free stores
    for (int idx = threadIdx.x; idx < 8 * C_; idx += 256) {
        int bb = idx >> 9;
        int c = idx & (C_ - 1);
        ct[c * 8 + bb] = clip[(b0 + bb) * C_ + c];
    }
    __syncthreads();
    float acc[8];
#pragma unroll
    for (int bb = 0; bb < 8; bb++) acc[bb] = 0.f;
    int cbase = cq * 128;
#pragma unroll 8
    for (int cc = 0; cc < 128; cc++) {
        int c = cbase + cc;
        float wq = __ldg(&Wq[(size_t)c * C_ + j]);
        float4 a = *(const float4*)&ct[c * 8];
        float4 b4 = *(const float4*)&ct[c * 8 + 4];
        acc[0] += a.x * wq; acc[1] += a.y * wq;
        acc[2] += a.z * wq; acc[3] += a.w * wq;
        acc[4] += b4.x * wq; acc[5] += b4.y * wq;
        acc[6] += b4.z * wq; acc[7] += b4.w * wq;
    }
#pragma unroll
    for (int bb = 0; bb < 8; bb++) pr[cq][jl][bb] = acc[bb];
    __syncthreads();
    if (threadIdx.x < 64) {
        int jj = blockIdx.x * 64 + threadIdx.x;
        float bqv = bq[jj];
#pragma unroll
        for (int bb = 0; bb < 8; bb++) {
            float s = pr[0][threadIdx.x][bb] + pr[1][threadIdx.x][bb] +
                      pr[2][threadIdx.x][bb] + pr[3][threadIdx.x][bb];
            g_Q[(size_t)(b0 + bb) * C_ + jj] = s + bqv;
        }
    }
}

// ---------- kernel 2: qk[b,h,f] = (sum_d Q[b,h*64+d] * Wk[f, h*64+d]) / (8*temp) ----------
// grid 64 (2 b per block), 384 threads (thread = f).
__global__ __launch_bounds__(384) void k_qk(const float* __restrict__ Wk,
                                            const float* __restrict__ temp) {
    int b0 = blockIdx.x * 2;
    int f = threadIdx.x;
    __shared__ float Qs[2 * C_];
    for (int idx = threadIdx.x; idx < 2 * C_; idx += 384)
        Qs[idx] = g_Q[(size_t)b0 * C_ + idx];
    __syncthreads();
    float inv = 1.0f / (8.0f * temp[0]);
    const float4* wk = (const float4*)(Wk + (size_t)f * C_);
    for (int h = 0; h < H_; h++) {
        float a0 = 0.f, a1 = 0.f;
#pragma unroll
        for (int t = 0; t < 16; t++) {
            float4 w4 = __ldg(wk + h * 16 + t);
            float4 qa = *(const float4*)&Qs[h * 64 + t * 4];
            float4 qb = *(const float4*)&Qs[C_ + h * 64 + t * 4];
            a0 += w4.x * qa.x + w4.y * qa.y + w4.z * qa.z + w4.w * qa.w;
            a1 += w4.x * qb.x + w4.y * qb.y + w4.z * qb.z + w4.w * qb.w;
        }
        g_qk[((size_t)b0 * H_ + h) * F_ + f] = a0 * inv;
        g_qk[((size_t)(b0 + 1) * H_ + h) * F_ + f] = a1 * inv;
    }
}

// ---------- kernel 3 (fused main): attention pass + Wv epilogue + LayerNorm ----------
// grid 128 (one block per b), 384 threads = 12 warps.
// Warp w: heads [4*(w&1), 4*(w&1)+4), rows n ≡ (w>>1) (mod 6).
__global__ __launch_bounds__(384, 1) void k_attn(const float* __restrict__ dino,
                                                 const float* __restrict__ Wv,
                                                 const float* __restrict__ bv,
                                                 const float* __restrict__ gamma,
                                                 const float* __restrict__ beta,
                                                 float* __restrict__ out) {
    int b = blockIdx.x;
    int tid = threadIdx.x;
    int w = tid >> 5, lane = tid & 31;
    int half = w & 1;   // which 4 heads
    int rg = w >> 1;    // row group 0..5

    __shared__ float sctx[H_ * F_];
    __shared__ float ssum[H_];
    __shared__ float red[32];
    for (int i = tid; i < H_ * F_; i += 384) sctx[i] = 0.f;
    if (tid < H_) ssum[tid] = 0.f;
    __syncthreads();

    // load qk for my 4 heads into packed regs
    unsigned long long qk2[4][6];
#pragma unroll
    for (int h = 0; h < 4; h++) {
#pragma unroll
        for (int c = 0; c < 3; c++) {
            float4 v = *(const float4*)&g_qk[((size_t)b * H_ + half * 4 + h) * F_ +
                                             (c * 32 + lane) * 4];
            qk2[h][2 * c] = pk2(v.x, v.y);
            qk2[h][2 * c + 1] = pk2(v.z, v.w);
        }
    }
    unsigned long long ctx2[4][6];
#pragma unroll
    for (int h = 0; h < 4; h++)
#pragma unroll
        for (int i = 0; i < 6; i++) ctx2[h][i] = 0ull;
    float s_acc = 0.f;   // per-lane: sum of weights for head (lane>>3)

    const float4* dbase = (const float4*)(dino + (size_t)b * N_ * F_);
    int n = rg;
    const float4* rp = dbase + (size_t)n * (F_ / 4) + lane;
    float4 p0 = __ldg(rp), p1 = __ldg(rp + 32), p2 = __ldg(rp + 64);

    while (n < N_) {
        float4 d0 = p0, d1 = p1, d2 = p2;
        int nn = n + 6;
        if (nn < N_) {
            const float4* np = dbase + (size_t)nn * (F_ / 4) + lane;
            p0 = __ldg(np); p1 = __ldg(np + 32); p2 = __ldg(np + 64);
        }
        unsigned long long dd[6] = {pk2(d0.x, d0.y), pk2(d0.z, d0.w),
                                    pk2(d1.x, d1.y), pk2(d1.z, d1.w),
                                    pk2(d2.x, d2.y), pk2(d2.z, d2.w)};
        // per-head partial dot (packed)
        float p[4];
#pragma unroll
        for (int h = 0; h < 4; h++) {
            unsigned long long acc = 0ull;
#pragma unroll
            for (int i = 0; i < 6; i++) ffma2(acc, dd[i], qk2[h][i]);
            float lo, hi;
            upk2(acc, lo, hi);
            p[h] = lo + hi;
        }
        // cheap 4-head reduction: butterfly(16,8) -> octet select -> butterfly(4,2,1)
#pragma unroll
        for (int h = 0; h < 4; h++) {
            p[h] += __shfl_xor_sync(0xffffffffu, p[h], 16);
            p[h] += __shfl_xor_sync(0xffffffffu, p[h], 8);
        }
        float v = (lane < 16) ? ((lane < 8) ? p[0] : p[1])
                              : ((lane < 24) ? p[2] : p[3]);
        v += __shfl_xor_sync(0xffffffffu, v, 4);
        v += __shfl_xor_sync(0xffffffffu, v, 2);
        v += __shfl_xor_sync(0xffffffffu, v, 1);
        // one exp per lane (lanes in octet h hold head h's full logit)
        float wexp = __expf(v);
        s_acc += wexp;
        float wh[4];
#pragma unroll
        for (int h = 0; h < 4; h++)
            wh[h] = __shfl_sync(0xffffffffu, wexp, h * 8);
#pragma unroll
        for (int h = 0; h < 4; h++) {
            unsigned long long w2 = pk2(wh[h], wh[h]);
#pragma unroll
            for (int i = 0; i < 6; i++) ffma2(ctx2[h][i], dd[i], w2);
        }
        n = nn;
    }

    // combine partials across the 6 row-group warps via smem atomics
#pragma unroll
    for (int h = 0; h < 4; h++) {
        int gh = half * 4 + h;
#pragma unroll
        for (int i = 0; i < 6; i++) {
            float lo, hi;
            upk2(ctx2[h][i], lo, hi);
            int fbase = ((i >> 1) * 32 + lane) * 4 + (i & 1) * 2;
            atomicAdd(&sctx[gh * F_ + fbase], lo);
            atomicAdd(&sctx[gh * F_ + fbase + 1], hi);
        }
    }
    if ((lane & 7) == 0)
        atomicAdd(&ssum[half * 4 + (lane >> 3)], s_acc);
    __syncthreads();

    // ---- fused epilogue: out = (sctx/ssum) @ Wv + bv, then LayerNorm ----
    float vals[2];
    float myv = 0.f, myq = 0.f;
#pragma unroll
    for (int rep = 0; rep < 2; rep++) {
        int j = tid + rep * 384;
        if (j < C_) {
            int h = j >> 6;
            const float* cp = &sctx[h * F_];
            float inv = 1.0f / ssum[h];
            float acc = 0.f;
#pragma unroll 8
            for (int f = 0; f < F_; f++)
                acc += cp[f] * __ldg(&Wv[(size_t)f * C_ + j]);
            float val = acc * inv + bv[j];
            vals[rep] = val;
            myv += val;
            myq += val * val;
        }
    }
#pragma unroll
    for (int o = 16; o; o >>= 1) {
        myv += __shfl_xor_sync(0xffffffffu, myv, o);
        myq += __shfl_xor_sync(0xffffffffu, myq, o);
    }
    if (lane == 0) { red[w] = myv; red[12 + w] = myq; }
    __syncthreads();
    if (tid == 0) {
        float sv = 0.f, sq = 0.f;
#pragma unroll
        for (int k = 0; k < 12; k++) { sv += red[k]; sq += red[12 + k]; }
        float mu = sv * (1.0f / C_);
        float var = sq * (1.0f / C_) - mu * mu;
        red[24] = mu;
        red[25] = rsqrtf(var + 1e-5f);
    }
    __syncthreads();
    float mu = red[24], rs = red[25];
#pragma unroll
    for (int rep = 0; rep < 2; rep++) {
        int j = tid + rep * 384;
        if (j < C_)
            out[(size_t)b * C_ + j] = (vals[rep] - mu) * rs * gamma[j] + beta[j];
    }
}

extern "C" void kernel_launch(void* const* d_in, const int* in_sizes, int n_in,
                              void* d_out, int out_size) {
    const float* dino = (const float*)d_in[0];
    const float* clip = (const float*)d_in[1];
    const float* Wq = (const float*)d_in[2];
    const float* bq = (const float*)d_in[3];
    const float* Wk = (const float*)d_in[4];
    // d_in[5] = bk: cancels exactly in softmax (n-invariant logit shift)
    const float* Wv = (const float*)d_in[6];
    const float* bv = (const float*)d_in[7];
    const float* temp = (const float*)d_in[8];
    const float* gamma = (const float*)d_in[9];
    const float* beta = (const float*)d_in[10];
    float* out = (float*)d_out;

    k_qproj<<<dim3(8, 16), 256>>>(clip, Wq, bq);
    k_qk<<<64, 384>>>(Wk, temp);
    k_attn<<<128, 384>>>(dino, Wv, bv, gamma, beta, out);
}